// round 8
// baseline (speedup 1.0000x reference)
#include <cuda_runtime.h>
#include <cuda_bf16.h>

// WeldonPool2d: per row of N=1024 floats, out = (mean(top10) + mean(bottom10)) / 2.
//
// R8 = R7 (pruned constexpr Batcher net, template expansion, smem-window
// extraction) + two changes:
//  (1) fma-pipe CEs are now 4 FADDs producing (2*min, 2*max) — the /2 is
//      deferred. Applied ONLY to the four half-cleaner layers (p==k<=8),
//      which touch all 32 wires, so every value is scaled by exactly 2^4=16
//      and all later comparisons remain order-correct. Final constant is
//      0.05/16 (exact). static_assert checks all 64 such CEs survive pruning.
//  (2) one warp handles TWO rows: sorts run back-to-back reusing v[32];
//      the 10-round extraction then runs 4 independent chains (top/bottom x
//      row0/row1) to lift issue efficiency (R7: issue=77%, nothing saturated).

#define WPB 4
#define THREADS (WPB * 32)
#define ROW_N 1024
#define WIN_STRIDE 43   // 40 floats/lane + 3 pad; 43 coprime w/ 32 banks

struct Net {
    short a[256];
    short b[256];
    bool  fm[256];
    int   n;
};

constexpr Net make_net() {
    constexpr int N = 32;
    short fa[256] = {}, fb[256] = {};
    bool  ff[256] = {};
    int m = 0;
    for (int p = 1; p < N; p <<= 1)
        for (int k = p; k >= 1; k >>= 1)
            for (int j = k % p; j + k < N; j += 2 * k)
                for (int i = 0; i < k && i + j + k < N; i++)
                    if ((i + j) / (2 * p) == (i + j + k) / (2 * p)) {
                        fa[m] = (short)(i + j);
                        fb[m] = (short)(i + j + k);
                        ff[m] = (k == p && p <= 8);  // half-cleaner layers p=1,2,4,8
                        m++;
                    }
    // Backward liveness pruning: consumed outputs are 0..9 and 22..31.
    bool live[N] = {};
    for (int i = 0; i < N; i++) live[i] = (i <= 9) || (i >= 22);
    bool keep[256] = {};
    for (int t = m - 1; t >= 0; t--) {
        if (live[fa[t]] || live[fb[t]]) {
            keep[t] = true;
            live[fa[t]] = true;
            live[fb[t]] = true;
        }
    }
    Net net{};
    net.n = 0;
    for (int t = 0; t < m; t++)
        if (keep[t]) {
            net.a[net.n] = fa[t];
            net.b[net.n] = fb[t];
            net.fm[net.n] = ff[t];
            net.n++;
        }
    return net;
}

constexpr Net NET = make_net();

constexpr int fma_count() {
    int c = 0;
    for (int i = 0; i < NET.n; i++) c += NET.fm[i] ? 1 : 0;
    return c;
}
// All 4 scaling layers (4 x 16 CEs) must survive pruning, else scales diverge.
static_assert(fma_count() == 64, "scaling half-cleaner layers must be intact");

// Every value passes exactly 4 scaling layers -> x16; fold into output const.
#define OUT_SCALE 0.003125f   // 0.05 / 16

// Exact CE on the ALU pipe (2x FMNMX).
__device__ __forceinline__ void ce_alu(float& lo, float& hi) {
    float x = lo, y = hi;
    lo = fminf(x, y);
    hi = fmaxf(x, y);
}
// 4-FADD CE on the FMA pipe producing (2*min, 2*max); ~1-ulp relative error.
__device__ __forceinline__ void ce_fma2(float& lo, float& hi) {
    float x = lo, y = hi;
    float s = x + y;
    float d = x - y;
    lo = s - fabsf(d);
    hi = s + fabsf(d);
}

template <int T>
__device__ __forceinline__ void sort_net(float (&v)[32]) {
    if constexpr (T < NET.n) {
        constexpr int A = NET.a[T];
        constexpr int B = NET.b[T];
        if constexpr (NET.fm[T])
            ce_fma2(v[A], v[B]);
        else
            ce_alu(v[A], v[B]);
        sort_net<T + 1>(v);
    }
}

__global__ void __launch_bounds__(THREADS, 9)
weldon_kernel(const float* __restrict__ x, float* __restrict__ out, int rows) {
    __shared__ float win[WPB][32 * WIN_STRIDE];

    const int wib  = threadIdx.x >> 5;
    const int warp = blockIdx.x * WPB + wib;   // one warp = one row PAIR
    const int lane = threadIdx.x & 31;
    const int r0 = 2 * warp;
    if (r0 >= rows) return;

    float* w = &win[wib][lane * WIN_STRIDE];
    // layout per lane: [0..9]=top row0 desc, [10..19]=bot row0 asc,
    //                  [20..29]=top row1 desc, [30..39]=bot row1 asc
    const float4* p0 = reinterpret_cast<const float4*>(x) + (size_t)r0 * (ROW_N / 4);
    const float4* p1 = p0 + (ROW_N / 4);

    float v[32];
    float ht0, hb0;

    // ---- row 0: load, sort, spill window ----
    {
#pragma unroll
        for (int i = 0; i < 8; i++) {
            float4 q = __ldg(&p0[lane + 32 * i]);
            v[4 * i + 0] = q.x;
            v[4 * i + 1] = q.y;
            v[4 * i + 2] = q.z;
            v[4 * i + 3] = q.w;
        }
        sort_net<0>(v);
#pragma unroll
        for (int i = 0; i < 10; i++) {
            w[i]      = v[31 - i];
            w[10 + i] = v[i];
        }
        ht0 = v[31];
        hb0 = v[0];
    }

    // ---- row 1: load, sort, spill window (reuses v registers) ----
#pragma unroll
    for (int i = 0; i < 8; i++) {
        float4 q = __ldg(&p1[lane + 32 * i]);
        v[4 * i + 0] = q.x;
        v[4 * i + 1] = q.y;
        v[4 * i + 2] = q.z;
        v[4 * i + 3] = q.w;
    }
    sort_net<0>(v);
#pragma unroll
    for (int i = 0; i < 10; i++) {
        w[20 + i] = v[31 - i];
        w[30 + i] = v[i];
    }
    float ht1 = v[31];
    float hb1 = v[0];

    // ---- 10 extraction rounds, 4 independent chains ----
    int ct0 = 0, cb0 = 10, ct1 = 20, cb1 = 30;
    float sT0 = 0.f, sB0 = 0.f, sT1 = 0.f, sB1 = 0.f;

#pragma unroll
    for (int r = 0; r < 10; r++) {
        float mT0 = ht0, mB0 = hb0, mT1 = ht1, mB1 = hb1;
#pragma unroll
        for (int off = 16; off > 0; off >>= 1) {
            mT0 = fmaxf(mT0, __shfl_xor_sync(0xffffffffu, mT0, off));
            mB0 = fminf(mB0, __shfl_xor_sync(0xffffffffu, mB0, off));
            mT1 = fmaxf(mT1, __shfl_xor_sync(0xffffffffu, mT1, off));
            mB1 = fminf(mB1, __shfl_xor_sync(0xffffffffu, mB1, off));
        }
        sT0 += mT0; sB0 += mB0; sT1 += mT1; sB1 += mB1;

        if (r < 9) {
            unsigned kT0 = __ballot_sync(0xffffffffu, ht0 == mT0);
            unsigned kB0 = __ballot_sync(0xffffffffu, hb0 == mB0);
            unsigned kT1 = __ballot_sync(0xffffffffu, ht1 == mT1);
            unsigned kB1 = __ballot_sync(0xffffffffu, hb1 == mB1);
            int oT0 = (lane == __ffs(kT0) - 1);
            int oB0 = (lane == __ffs(kB0) - 1);
            int oT1 = (lane == __ffs(kT1) - 1);
            int oB1 = (lane == __ffs(kB1) - 1);
            ct0 += oT0; cb0 += oB0; ct1 += oT1; cb1 += oB1;
            float nT0 = w[ct0];
            float nB0 = w[cb0];
            float nT1 = w[ct1];
            float nB1 = w[cb1];
            ht0 = oT0 ? nT0 : ht0;
            hb0 = oB0 ? nB0 : hb0;
            ht1 = oT1 ? nT1 : ht1;
            hb1 = oB1 ? nB1 : hb1;
        }
    }

    if (lane == 0) {
        out[r0]     = (sT0 + sB0) * OUT_SCALE;
        out[r0 + 1] = (sT1 + sB1) * OUT_SCALE;
    }
}

extern "C" void kernel_launch(void* const* d_in, const int* in_sizes, int n_in,
                              void* d_out, int out_size) {
    const float* x = (const float*)d_in[0];
    float* out = (float*)d_out;
    const int rows = in_sizes[0] / ROW_N;   // 65536 (even)
    const int pairs = rows / 2;
    const int blocks = (pairs + WPB - 1) / WPB;
    weldon_kernel<<<blocks, THREADS>>>(x, out, rows);
}

// round 9
// speedup vs baseline: 1.0009x; 1.0009x over previous
#include <cuda_runtime.h>
#include <cuda_bf16.h>

// WeldonPool2d: per row of N=1024 floats, out = (mean(top10) + mean(bottom10)) / 2.
//
// R9 = R7 structure (1 row/warp, pruned constexpr Batcher net, template
// expansion, smem-window extraction) with the fma offload RE-CALIBRATED.
// R7/R8 measurements show ISSUE SLOTS bind (798/row) while the alu pipe sits
// at 690 equiv -> offload only x=32 CEs (balance point of
// min max(issues, 2*alu)), and use a 4-FADD scale-deferred CE:
//   s=a+b; d=a-b; lo=s-|d|; hi=s+|d|   (produces 2*min, 2*max)
// applied to the two full layers (p=1,k=1) and (p=2,k=2) that touch every
// wire exactly once -> every value scaled by exactly 4; OUT_SCALE = 0.05/4.

#define WARPS_PER_BLOCK 8
#define THREADS (WARPS_PER_BLOCK * 32)
#define ROW_N 1024
#define WIN_STRIDE 21   // 20 floats per lane + 1 pad

struct Net {
    short a[256];
    short b[256];
    bool  fm[256];
    int   n;
};

constexpr Net make_net() {
    constexpr int N = 32;
    short fa[256] = {}, fb[256] = {};
    bool  ff[256] = {};
    int m = 0;
    for (int p = 1; p < N; p <<= 1)
        for (int k = p; k >= 1; k >>= 1)
            for (int j = k % p; j + k < N; j += 2 * k)
                for (int i = 0; i < k && i + j + k < N; i++)
                    if ((i + j) / (2 * p) == (i + j + k) / (2 * p)) {
                        fa[m] = (short)(i + j);
                        fb[m] = (short)(i + j + k);
                        ff[m] = (k == p && p <= 2);  // scaling layers p=1, p=2
                        m++;
                    }
    // Backward liveness pruning: consumed outputs are 0..9 and 22..31.
    bool live[N] = {};
    for (int i = 0; i < N; i++) live[i] = (i <= 9) || (i >= 22);
    bool keep[256] = {};
    for (int t = m - 1; t >= 0; t--) {
        if (live[fa[t]] || live[fb[t]]) {
            keep[t] = true;
            live[fa[t]] = true;
            live[fb[t]] = true;
        }
    }
    Net net{};
    net.n = 0;
    for (int t = 0; t < m; t++)
        if (keep[t]) {
            net.a[net.n] = fa[t];
            net.b[net.n] = fb[t];
            net.fm[net.n] = ff[t];
            net.n++;
        }
    return net;
}

constexpr Net NET = make_net();

constexpr int fma_count() {
    int c = 0;
    for (int i = 0; i < NET.n; i++) c += NET.fm[i] ? 1 : 0;
    return c;
}
// Both 16-CE scaling layers must survive pruning, else per-value scales diverge.
static_assert(fma_count() == 32, "scaling layers p=1,p=2 must be intact");

// Every value passes exactly 2 scaling layers -> x4; fold into output const.
#define OUT_SCALE 0.0125f   // 0.05 / 4  (exact)

// Exact CE on the ALU pipe (2x FMNMX).
__device__ __forceinline__ void ce_alu(float& lo, float& hi) {
    float x = lo, y = hi;
    lo = fminf(x, y);
    hi = fmaxf(x, y);
}
// 4-FADD CE on the FMA pipe producing (2*min, 2*max); ~1-ulp relative error.
__device__ __forceinline__ void ce_fma2(float& lo, float& hi) {
    float x = lo, y = hi;
    float s = x + y;
    float d = x - y;
    lo = s - fabsf(d);
    hi = s + fabsf(d);
}

template <int T>
__device__ __forceinline__ void sort_net(float (&v)[32]) {
    if constexpr (T < NET.n) {
        constexpr int A = NET.a[T];
        constexpr int B = NET.b[T];
        if constexpr (NET.fm[T])
            ce_fma2(v[A], v[B]);
        else
            ce_alu(v[A], v[B]);
        sort_net<T + 1>(v);
    }
}

__global__ void __launch_bounds__(THREADS)
weldon_kernel(const float* __restrict__ x, float* __restrict__ out, int rows) {
    __shared__ float win[WARPS_PER_BLOCK][32 * WIN_STRIDE];

    const int wib  = threadIdx.x >> 5;
    const int warp = blockIdx.x * WARPS_PER_BLOCK + wib;
    const int lane = threadIdx.x & 31;
    if (warp >= rows) return;

    // ---- Load 32 elements per lane as 8 coalesced float4 ----
    const float4* p = reinterpret_cast<const float4*>(x) + (size_t)warp * (ROW_N / 4);
    float v[32];
#pragma unroll
    for (int i = 0; i < 8; i++) {
        float4 q = __ldg(&p[lane + 32 * i]);
        v[4 * i + 0] = q.x;
        v[4 * i + 1] = q.y;
        v[4 * i + 2] = q.z;
        v[4 * i + 3] = q.w;
    }

    // ---- Pruned Batcher sort (ascending x4-scaled; outputs 0..9, 22..31) ----
    sort_net<0>(v);

    // ---- Spill per-lane windows to smem (heads stay in registers) ----
    // w[1..9]   = top candidates 2..10 descending
    // w[11..19] = bottom candidates 2..10 ascending
    float* w = &win[wib][lane * WIN_STRIDE];
#pragma unroll
    for (int i = 1; i < 10; i++) {
        w[i]      = v[31 - i];
        w[10 + i] = v[i];
    }

    // ---- 10 extraction rounds; heads in registers, pops via cursor+LDS ----
    float ht = v[31];
    float hb = v[0];
    int ct = 0;
    int cb = 10;
    float sT = 0.0f, sB = 0.0f;

#pragma unroll
    for (int r = 0; r < 10; r++) {
        float m = ht;
#pragma unroll
        for (int off = 16; off > 0; off >>= 1)
            m = fmaxf(m, __shfl_xor_sync(0xffffffffu, m, off));
        sT += m;
        unsigned mk = __ballot_sync(0xffffffffu, ht == m);
        int own = (lane == __ffs(mk) - 1);
        if (r < 9) {
            ct += own;
            float nt = w[ct];      // non-owners read w[ct] and discard
            ht = own ? nt : ht;
        }

        float mm = hb;
#pragma unroll
        for (int off = 16; off > 0; off >>= 1)
            mm = fminf(mm, __shfl_xor_sync(0xffffffffu, mm, off));
        sB += mm;
        unsigned mk2 = __ballot_sync(0xffffffffu, hb == mm);
        int own2 = (lane == __ffs(mk2) - 1);
        if (r < 9) {
            cb += own2;
            float nb = w[cb];
            hb = own2 ? nb : hb;
        }
    }

    if (lane == 0) out[warp] = (sT + sB) * OUT_SCALE;
}

extern "C" void kernel_launch(void* const* d_in, const int* in_sizes, int n_in,
                              void* d_out, int out_size) {
    const float* x = (const float*)d_in[0];
    float* out = (float*)d_out;
    const int rows = in_sizes[0] / ROW_N;  // 65536
    const int blocks = (rows + WARPS_PER_BLOCK - 1) / WARPS_PER_BLOCK;
    weldon_kernel<<<blocks, THREADS>>>(x, out, rows);
}